// round 1
// baseline (speedup 1.0000x reference)
#include <cuda_runtime.h>
#include <cstdint>

#define NT    256     // threads per block (main kernel)
#define PPT   2       // priors per thread
#define MAXT  512
#define MAXP  65536
#define NWARP (NT / 32)

// Scratch (no allocations allowed)
__device__ unsigned long long g_best[MAXT];     // per-truth packed (iou_bits<<32 | ~p)
__device__ unsigned long long g_scatter[MAXP];  // per-prior packed ((t+1)<<32 | iou_bits)
__device__ float              g_bto[MAXP];      // best_truth_overlap (pre-scatter)
__device__ float              g_sums[3];

__global__ void k_init(int T) {
    int i = threadIdx.x;
    if (i < T) g_best[i] = 0ull;
    if (i < 3) g_sums[i] = 0.0f;
}

__global__ void k_main(const float* __restrict__ locs,
                       const float* __restrict__ params,
                       const float4* __restrict__ truths,
                       int P, int T) {
    __shared__ float4 s_tr[MAXT];
    __shared__ float  s_ta[MAXT];
    __shared__ unsigned long long s_best[MAXT * NWARP];  // per (t, warp) winner

    const int tid  = threadIdx.x;
    const int lane = tid & 31;
    const int wid  = tid >> 5;

    for (int t = tid; t < T; t += NT) {
        float4 tb = truths[t];
        s_tr[t] = tb;
        s_ta[t] = (tb.z - tb.x) * (tb.w - tb.y);
    }
    for (int i = tid; i < T * NWARP; i += NT) s_best[i] = 0ull;
    __syncthreads();

    const int p0 = blockIdx.x * (NT * PPT) + tid;

    float x0[PPT], y0[PPT], x1[PPT], y1[PPT], ab[PPT], bi[PPT], bu[PPT];
#pragma unroll
    for (int j = 0; j < PPT; j++) {
        int p = p0 + j * NT;
        float cx, cy, w, h;
        if (p < P) {
            float2 c = ((const float2*)locs)[p];
            cx = c.x; cy = c.y;
            w = params[3 * p];
            h = params[3 * p + 1];
            g_scatter[p] = 0ull;  // clear scatter buffer for this launch
        } else {
            cx = -100.0f; cy = -100.0f; w = 0.0f; h = 0.0f;
        }
        x0[j] = cx - 0.5f * w;  x1[j] = cx + 0.5f * w;
        y0[j] = cy - 0.5f * h;  y1[j] = cy + 0.5f * h;
        ab[j] = w * h;
        bi[j] = 0.0f;           // best inter  (per-prior, over t)
        bu[j] = 1.0f;           // best union
    }

    for (int t = 0; t < T; t++) {
        const float4 tb = s_tr[t];
        const float  ta = s_ta[t];

        // per-truth best across this thread's priors
        float bti = 0.0f, btu = 1.0f;
        int   btp = p0;

#pragma unroll
        for (int j = 0; j < PPT; j++) {
            float dx = fminf(x1[j], tb.z) - fmaxf(x0[j], tb.x);
            float dy = fminf(y1[j], tb.w) - fmaxf(y0[j], tb.y);
            float inter = fmaxf(dx, 0.0f) * fmaxf(dy, 0.0f);
            float uni   = ta + ab[j] - inter;  // > 0 always (areas > 0)
            // max over t for this prior (ratio compare, no division)
            if (inter * bu[j] > bi[j] * uni) { bi[j] = inter; bu[j] = uni; }
            // max over this thread's priors for truth t
            if (inter * btu > bti * uni) { bti = inter; btu = uni; btp = p0 + j * NT; }
        }

        // warp-level reduce of (inter, union, p) via ratio compare
#pragma unroll
        for (int off = 16; off > 0; off >>= 1) {
            float oi = __shfl_xor_sync(0xffffffffu, bti, off);
            float ou = __shfl_xor_sync(0xffffffffu, btu, off);
            int   op = __shfl_xor_sync(0xffffffffu, btp, off);
            if (oi * btu > bti * ou) { bti = oi; btu = ou; btp = op; }
        }
        if (lane == 0) {
            float iou = __fdividef(bti, btu);  // approx OK: only ranks candidates;
                                               // exact value recomputed in k_scatter
            s_best[t * NWARP + wid] =
                (((unsigned long long)__float_as_uint(iou)) << 32) |
                (unsigned int)(~btp);          // ~p => ties pick smallest index
        }
    }
    __syncthreads();

    // block combine + one global atomic per truth per block
    for (int t = tid; t < T; t += NT) {
        unsigned long long m = s_best[t * NWARP];
#pragma unroll
        for (int w = 1; w < NWARP; w++) {
            unsigned long long v = s_best[t * NWARP + w];
            if (v > m) m = v;
        }
        atomicMax(&g_best[t], m);
    }

    // per-prior best_truth_overlap (exact division)
#pragma unroll
    for (int j = 0; j < PPT; j++) {
        int p = p0 + j * NT;
        if (p < P) g_bto[p] = bi[j] / bu[j];
    }
}

// One thread per truth: recompute EXACT iou at the selected argmax prior and
// scatter with last-t-wins semantics (matches CPU-XLA duplicate-index scatter).
__global__ void k_scatter(const float* __restrict__ locs,
                          const float* __restrict__ params,
                          const float4* __restrict__ truths, int T) {
    int t = blockIdx.x * blockDim.x + threadIdx.x;
    if (t >= T) return;
    unsigned long long m = g_best[t];
    unsigned int p = ~((unsigned int)(m & 0xffffffffull));
    float4 tb = truths[t];
    float2 c = ((const float2*)locs)[p];
    float w = params[3 * p];
    float h = params[3 * p + 1];
    float px0 = c.x - 0.5f * w, px1 = c.x + 0.5f * w;
    float py0 = c.y - 0.5f * h, py1 = c.y + 0.5f * h;
    float dx = fminf(px1, tb.z) - fmaxf(px0, tb.x);
    float dy = fminf(py1, tb.w) - fmaxf(py0, tb.y);
    float inter = fmaxf(dx, 0.0f) * fmaxf(dy, 0.0f);
    float ta = (tb.z - tb.x) * (tb.w - tb.y);
    float iou = inter / (ta + w * h - inter);
    unsigned long long pk =
        (((unsigned long long)(t + 1)) << 32) | __float_as_uint(iou);
    atomicMax(&g_scatter[p], pk);
}

__global__ void k_reduce(const float* __restrict__ params, int P) {
    int p = blockIdx.x * blockDim.x + threadIdx.x;
    float s0 = 0.0f, s1 = 0.0f, s2 = 0.0f;
    if (p < P) {
        float bto = g_bto[p];
        unsigned long long sc = g_scatter[p];
        bool isbest = (sc != 0ull);
        if (isbest) bto = __uint_as_float((unsigned int)(sc & 0xffffffffull));
        float xf = isbest ? 5.0f : (bto > 0.5f ? 1.0f : 0.0f);
        float a = params[3 * p + 2];
        float sig = 1.0f / (1.0f + __expf(-a));
        s0 = sig * xf * bto;
        s1 = sig;          // BETA = 1
        s2 = xf;
    }
#pragma unroll
    for (int off = 16; off > 0; off >>= 1) {
        s0 += __shfl_xor_sync(0xffffffffu, s0, off);
        s1 += __shfl_xor_sync(0xffffffffu, s1, off);
        s2 += __shfl_xor_sync(0xffffffffu, s2, off);
    }
    __shared__ float sh0[8], sh1[8], sh2[8];
    int lane = threadIdx.x & 31, wid = threadIdx.x >> 5;
    if (lane == 0) { sh0[wid] = s0; sh1[wid] = s1; sh2[wid] = s2; }
    __syncthreads();
    if (wid == 0) {
        s0 = (lane < 8) ? sh0[lane] : 0.0f;
        s1 = (lane < 8) ? sh1[lane] : 0.0f;
        s2 = (lane < 8) ? sh2[lane] : 0.0f;
#pragma unroll
        for (int off = 4; off > 0; off >>= 1) {
            s0 += __shfl_xor_sync(0xffffffffu, s0, off);
            s1 += __shfl_xor_sync(0xffffffffu, s1, off);
            s2 += __shfl_xor_sync(0xffffffffu, s2, off);
        }
        if (lane == 0) {
            atomicAdd(&g_sums[0], s0);
            atomicAdd(&g_sums[1], s1);
            atomicAdd(&g_sums[2], s2);
        }
    }
}

__global__ void k_final(float* __restrict__ out) {
    out[0] = (g_sums[0] + g_sums[1]) / g_sums[2];
}

extern "C" void kernel_launch(void* const* d_in, const int* in_sizes, int n_in,
                              void* d_out, int out_size) {
    const float*  locs   = (const float*)d_in[0];
    const float*  params = (const float*)d_in[1];
    const float4* truths = (const float4*)d_in[2];
    int P = in_sizes[0] / 2;
    int T = in_sizes[2] / 4;

    k_init<<<1, MAXT>>>(T);
    int nb = (P + NT * PPT - 1) / (NT * PPT);
    k_main<<<nb, NT>>>(locs, params, truths, P, T);
    k_scatter<<<(T + 255) / 256, 256>>>(locs, params, truths, T);
    k_reduce<<<(P + 255) / 256, 256>>>(params, P);
    k_final<<<1, 1>>>((float*)d_out);
}

// round 3
// speedup vs baseline: 2.3446x; 2.3446x over previous
#include <cuda_runtime.h>
#include <cstdint>

#define NT     256
#define PPT    8
#define NTCH   16
#define MAXT   512
#define MAXP   65536
#define NWARP  (NT / 32)
#define PPB    (NT * PPT)   // 2048 priors per block
#define TCHMAX 64           // max truths per chunk (shared-mem bound)

// Scratch (no allocations allowed)
__device__ unsigned long long g_best[MAXT];            // per-truth packed (iou_bits<<32 | ~p)
__device__ unsigned long long g_scatter[MAXP];         // per-prior packed ((t+1)<<32 | iou_bits)
__device__ float              g_bto_part[NTCH * MAXP]; // per-(tchunk, prior) best overlap
__device__ float              g_sums[3];

__global__ void k_init(int P, int T) {
    int i = blockIdx.x * blockDim.x + threadIdx.x;
    if (i < T) g_best[i] = 0ull;
    if (i < P) g_scatter[i] = 0ull;
    if (i < 3) g_sums[i] = 0.0f;
}

__global__ void __launch_bounds__(NT, 2)
k_main(const float2* __restrict__ locs,
       const float*  __restrict__ params,
       const float4* __restrict__ truths,
       int P, int T, int pblocks, int tch) {
    __shared__ float4 s_tr[TCHMAX];
    __shared__ float  s_ta[TCHMAX];
    __shared__ unsigned long long s_best[TCHMAX * NWARP];

    const int pb  = blockIdx.x % pblocks;
    const int tc  = blockIdx.x / pblocks;
    const int t0  = tc * tch;
    const int t1  = min(min(t0 + tch, T), t0 + TCHMAX);
    const int tid = threadIdx.x;
    const int lane = tid & 31;
    const int wid  = tid >> 5;

    for (int t = t0 + tid; t < t1; t += NT) {
        float4 tb = truths[t];
        s_tr[t - t0] = tb;
        s_ta[t - t0] = (tb.z - tb.x) * (tb.w - tb.y);
    }
    __syncthreads();

    const int pbase = pb * PPB + tid;

    float x0[PPT], y0[PPT], x1[PPT], y1[PPT], ab[PPT], bi[PPT], bu[PPT];
#pragma unroll
    for (int j = 0; j < PPT; j++) {
        int p = pbase + j * NT;
        float cx, cy, w, h;
        if (p < P) {
            float2 c = locs[p];
            cx = c.x; cy = c.y;
            w = params[3 * p];
            h = params[3 * p + 1];
        } else {
            cx = -1e3f; cy = -1e3f; w = 0.0f; h = 0.0f;
        }
        x0[j] = cx - 0.5f * w;  x1[j] = cx + 0.5f * w;
        y0[j] = cy - 0.5f * h;  y1[j] = cy + 0.5f * h;
        ab[j] = w * h;
        bi[j] = 0.0f;           // best inter over t (per prior)
        bu[j] = 1.0f;           // best union
    }

    for (int tt = t0; tt < t1; ++tt) {
        const float4 tb = s_tr[tt - t0];
        const float  ta = s_ta[tt - t0];

        float bti = 0.0f, btu = 1.0f;  // best over this thread's priors for truth tt
        int   btp = pbase;

#pragma unroll
        for (int j = 0; j < PPT; j++) {
            float dx = fminf(x1[j], tb.z) - fmaxf(x0[j], tb.x);
            float dy = fminf(y1[j], tb.w) - fmaxf(y0[j], tb.y);
            float inter = fmaxf(dx, 0.0f) * fmaxf(dy, 0.0f);
            float uni   = (ta + ab[j]) - inter;   // > 0 always (areas strictly positive)
            if (inter * bu[j] > bi[j] * uni) { bi[j] = inter; bu[j] = uni; }
            if (inter * btu   > bti   * uni) { bti = inter; btu = uni; btp = pbase + j * NT; }
        }

        // warp reduce (ratio compare, no division in hot path)
#pragma unroll
        for (int off = 16; off > 0; off >>= 1) {
            float oi = __shfl_xor_sync(0xffffffffu, bti, off);
            float ou = __shfl_xor_sync(0xffffffffu, btu, off);
            int   op = __shfl_xor_sync(0xffffffffu, btp, off);
            if (oi * btu > bti * ou) { bti = oi; btu = ou; btp = op; }
        }
        if (lane == 0) {
            float iou = __fdividef(bti, btu);  // ranking only; exact recompute in k_scatter
            s_best[(tt - t0) * NWARP + wid] =
                (((unsigned long long)__float_as_uint(iou)) << 32) |
                (unsigned int)(~btp);          // ~p => ties pick smallest prior index
        }
    }
    __syncthreads();

    // block combine + one global atomic per truth per block
    for (int tt = t0 + tid; tt < t1; tt += NT) {
        unsigned long long m = s_best[(tt - t0) * NWARP];
#pragma unroll
        for (int w = 1; w < NWARP; w++) {
            unsigned long long v = s_best[(tt - t0) * NWARP + w];
            if (v > m) m = v;
        }
        atomicMax(&g_best[tt], m);
    }

    // per-(tchunk, prior) best_truth_overlap partial (exact division, off hot path)
    float* part = g_bto_part + (size_t)tc * MAXP;
#pragma unroll
    for (int j = 0; j < PPT; j++) {
        int p = pbase + j * NT;
        if (p < P) part[p] = bi[j] / bu[j];
    }
}

// One thread per truth: recompute EXACT iou at the selected argmax prior and
// scatter with last-t-wins semantics (matches duplicate-index scatter).
__global__ void k_scatter(const float2* __restrict__ locs,
                          const float*  __restrict__ params,
                          const float4* __restrict__ truths, int T) {
    int t = blockIdx.x * blockDim.x + threadIdx.x;
    if (t >= T) return;
    unsigned long long m = g_best[t];
    unsigned int p = ~((unsigned int)(m & 0xffffffffull));
    float4 tb = truths[t];
    float2 c = locs[p];
    float w = params[3 * p];
    float h = params[3 * p + 1];
    float px0 = c.x - 0.5f * w, px1 = c.x + 0.5f * w;
    float py0 = c.y - 0.5f * h, py1 = c.y + 0.5f * h;
    float dx = fminf(px1, tb.z) - fmaxf(px0, tb.x);
    float dy = fminf(py1, tb.w) - fmaxf(py0, tb.y);
    float inter = fmaxf(dx, 0.0f) * fmaxf(dy, 0.0f);
    float ta = (tb.z - tb.x) * (tb.w - tb.y);
    float iou = inter / (ta + w * h - inter);
    unsigned long long pk =
        (((unsigned long long)(t + 1)) << 32) | __float_as_uint(iou);
    atomicMax(&g_scatter[p], pk);
}

__global__ void k_reduce(const float* __restrict__ params, int P) {
    int p = blockIdx.x * blockDim.x + threadIdx.x;
    float s0 = 0.0f, s1 = 0.0f, s2 = 0.0f;
    if (p < P) {
        float bto = g_bto_part[p];
#pragma unroll
        for (int c = 1; c < NTCH; c++)
            bto = fmaxf(bto, g_bto_part[c * MAXP + p]);
        unsigned long long sc = g_scatter[p];
        bool isbest = (sc != 0ull);
        if (isbest) bto = __uint_as_float((unsigned int)(sc & 0xffffffffull));
        float xf = isbest ? 5.0f : (bto > 0.5f ? 1.0f : 0.0f);
        float a = params[3 * p + 2];
        float sig = 1.0f / (1.0f + __expf(-a));
        s0 = sig * xf * bto;
        s1 = sig;          // BETA = 1
        s2 = xf;
    }
#pragma unroll
    for (int off = 16; off > 0; off >>= 1) {
        s0 += __shfl_xor_sync(0xffffffffu, s0, off);
        s1 += __shfl_xor_sync(0xffffffffu, s1, off);
        s2 += __shfl_xor_sync(0xffffffffu, s2, off);
    }
    __shared__ float sh0[8], sh1[8], sh2[8];
    int lane = threadIdx.x & 31, wid = threadIdx.x >> 5;
    if (lane == 0) { sh0[wid] = s0; sh1[wid] = s1; sh2[wid] = s2; }
    __syncthreads();
    if (wid == 0) {
        s0 = (lane < 8) ? sh0[lane] : 0.0f;
        s1 = (lane < 8) ? sh1[lane] : 0.0f;
        s2 = (lane < 8) ? sh2[lane] : 0.0f;
#pragma unroll
        for (int off = 4; off > 0; off >>= 1) {
            s0 += __shfl_xor_sync(0xffffffffu, s0, off);
            s1 += __shfl_xor_sync(0xffffffffu, s1, off);
            s2 += __shfl_xor_sync(0xffffffffu, s2, off);
        }
        if (lane == 0) {
            atomicAdd(&g_sums[0], s0);
            atomicAdd(&g_sums[1], s1);
            atomicAdd(&g_sums[2], s2);
        }
    }
}

__global__ void k_final(float* __restrict__ out) {
    out[0] = (g_sums[0] + g_sums[1]) / g_sums[2];
}

extern "C" void kernel_launch(void* const* d_in, const int* in_sizes, int n_in,
                              void* d_out, int out_size) {
    const float2* locs   = (const float2*)d_in[0];
    const float*  params = (const float*)d_in[1];
    const float4* truths = (const float4*)d_in[2];
    int P = in_sizes[0] / 2;
    int T = in_sizes[2] / 4;

    int tch = (T + NTCH - 1) / NTCH;            // 32 for T=512 (fits TCHMAX)
    int pblocks = (P + PPB - 1) / PPB;          // 32 for P=65536

    k_init<<<(P + 255) / 256, 256>>>(P, T);
    k_main<<<pblocks * NTCH, NT>>>(locs, params, truths, P, T, pblocks, tch);
    k_scatter<<<(T + 255) / 256, 256>>>(locs, params, truths, T);
    k_reduce<<<(P + 255) / 256, 256>>>(params, P);
    k_final<<<1, 1>>>((float*)d_out);
}

// round 4
// speedup vs baseline: 2.6240x; 1.1192x over previous
#include <cuda_runtime.h>
#include <cstdint>

#define NT     256
#define PPT    8
#define NTCH   16
#define MAXT   512
#define MAXP   65536
#define NWARP  (NT / 32)
#define PPB    (NT * PPT)   // 2048 priors per block
#define TCHMAX 64

// Scratch (no allocations allowed)
__device__ unsigned long long g_best[MAXT];     // per-truth packed (iou_bits<<32 | ~p)
__device__ unsigned long long g_scatter[MAXP];  // per-prior packed ((t+1)<<32 | iou_bits)
__device__ unsigned           g_bto[MAXP];      // per-prior best overlap (float bits, >=0)
__device__ float              g_sums[3];
__device__ unsigned           g_ctr_main;
__device__ unsigned           g_ctr_red;

__global__ void k_init(int P, int T) {
    int i = blockIdx.x * blockDim.x + threadIdx.x;
    if (i < T) g_best[i] = 0ull;
    if (i < P) { g_scatter[i] = 0ull; g_bto[i] = 0u; }
    if (i == 0) {
        g_sums[0] = 0.0f; g_sums[1] = 0.0f; g_sums[2] = 0.0f;
        g_ctr_main = 0u;  g_ctr_red = 0u;
    }
}

__global__ void __launch_bounds__(NT, 2)
k_main(const float2* __restrict__ locs,
       const float*  __restrict__ params,
       const float4* __restrict__ truths,
       int P, int T, int pblocks, int tch, int nblocks) {
    __shared__ float4 s_tr[TCHMAX];
    __shared__ float  s_ta[TCHMAX];
    __shared__ unsigned long long s_best[TCHMAX * NWARP];
    __shared__ bool   s_last;

    const int pb  = blockIdx.x % pblocks;
    const int tc  = blockIdx.x / pblocks;
    const int t0  = tc * tch;
    const int t1  = min(min(t0 + tch, T), t0 + TCHMAX);
    const int tid = threadIdx.x;
    const int lane = tid & 31;
    const int wid  = tid >> 5;

    for (int t = t0 + tid; t < t1; t += NT) {
        float4 tb = truths[t];
        s_tr[t - t0] = tb;
        s_ta[t - t0] = (tb.z - tb.x) * (tb.w - tb.y);
    }
    __syncthreads();

    const int pbase = pb * PPB + tid;

    float x0[PPT], y0[PPT], x1[PPT], y1[PPT], ab[PPT], biou[PPT];
#pragma unroll
    for (int j = 0; j < PPT; j++) {
        int p = pbase + j * NT;
        float cx, cy, w, h;
        if (p < P) {
            float2 c = locs[p];
            cx = c.x; cy = c.y;
            w = params[3 * p];
            h = params[3 * p + 1];
        } else {
            cx = -1e3f; cy = -1e3f; w = 0.0f; h = 0.0f;
        }
        x0[j] = cx - 0.5f * w;  x1[j] = cx + 0.5f * w;
        y0[j] = cy - 0.5f * h;  y1[j] = cy + 0.5f * h;
        ab[j] = w * h;
        biou[j] = 0.0f;
    }

    for (int tt = t0; tt < t1; ++tt) {
        const float4 tb = s_tr[tt - t0];
        const float  ta = s_ta[tt - t0];

        float btiou = -1.0f;
        int   btp   = pbase;

#pragma unroll
        for (int j = 0; j < PPT; j++) {
            float dx    = fminf(x1[j], tb.z) - fmaxf(x0[j], tb.x);
            float dy    = fminf(y1[j], tb.w) - fmaxf(y0[j], tb.y);
            float inter = fmaxf(dx, 0.0f) * fmaxf(dy, 0.0f);
            float uni   = (ta + ab[j]) - inter;         // > 0 always
            float iou   = __fdividef(inter, uni);       // MUFU.RCP + FMUL (hidden pipe)
            biou[j] = fmaxf(biou[j], iou);              // per-prior max over t
            if (iou > btiou) { btiou = iou; btp = pbase + j * NT; }
        }

        // warp argmax: pack (iou_bits, ~p) -> u64 max; ~p => ties prefer smallest p
        unsigned long long m =
            (((unsigned long long)__float_as_uint(btiou)) << 32) |
            (unsigned int)(~btp);
#pragma unroll
        for (int off = 16; off > 0; off >>= 1) {
            unsigned long long o = __shfl_xor_sync(0xffffffffu, m, off);
            if (o > m) m = o;
        }
        if (lane == 0) s_best[(tt - t0) * NWARP + wid] = m;
    }
    __syncthreads();

    // block combine + one global atomic per truth per block
    for (int tt = t0 + tid; tt < t1; tt += NT) {
        unsigned long long m = s_best[(tt - t0) * NWARP];
#pragma unroll
        for (int w = 1; w < NWARP; w++) {
            unsigned long long v = s_best[(tt - t0) * NWARP + w];
            if (v > m) m = v;
        }
        atomicMax(&g_best[tt], m);
    }

    // per-prior best_truth_overlap via float-bits atomicMax (values >= 0)
#pragma unroll
    for (int j = 0; j < PPT; j++) {
        int p = pbase + j * NT;
        if (p < P) atomicMax(&g_bto[p], __float_as_uint(biou[j]));
    }

    // ---- last-block scatter: exact iou at each truth's argmax prior ----
    __threadfence();
    if (tid == 0)
        s_last = (atomicAdd(&g_ctr_main, 1u) == (unsigned)(nblocks - 1));
    __syncthreads();
    if (s_last) {
        __threadfence();
        for (int t = tid; t < T; t += NT) {
            unsigned long long m = g_best[t];
            unsigned int p = ~((unsigned int)(m & 0xffffffffull));
            float4 tb = truths[t];
            float2 c  = locs[p];
            float w = params[3 * p];
            float h = params[3 * p + 1];
            float dx = fminf(c.x + 0.5f * w, tb.z) - fmaxf(c.x - 0.5f * w, tb.x);
            float dy = fminf(c.y + 0.5f * h, tb.w) - fmaxf(c.y - 0.5f * h, tb.y);
            float inter = fmaxf(dx, 0.0f) * fmaxf(dy, 0.0f);
            float ta = (tb.z - tb.x) * (tb.w - tb.y);
            float iou = inter / (ta + w * h - inter);   // exact division
            unsigned long long pk =
                (((unsigned long long)(t + 1)) << 32) | __float_as_uint(iou);
            atomicMax(&g_scatter[p], pk);               // last-t-wins scatter
        }
    }
}

__global__ void k_reduce(const float* __restrict__ params,
                         float* __restrict__ out, int P, int nblocks) {
    __shared__ float sh0[NWARP], sh1[NWARP], sh2[NWARP];
    __shared__ bool  s_last;
    const int tid  = threadIdx.x;
    const int lane = tid & 31;
    const int wid  = tid >> 5;
    const int base = (blockIdx.x * blockDim.x + tid) * 4;

    float s0 = 0.0f, s1 = 0.0f, s2 = 0.0f;
#pragma unroll
    for (int j = 0; j < 4; j++) {
        int p = base + j;
        if (p < P) {
            float bto = __uint_as_float(g_bto[p]);
            unsigned long long sc = g_scatter[p];
            bool isbest = (sc != 0ull);
            if (isbest) bto = __uint_as_float((unsigned int)(sc & 0xffffffffull));
            float xf = isbest ? 5.0f : (bto > 0.5f ? 1.0f : 0.0f);
            float a = params[3 * p + 2];
            float sig = 1.0f / (1.0f + __expf(-a));
            s0 += sig * xf * bto;
            s1 += sig;          // BETA = 1
            s2 += xf;
        }
    }
#pragma unroll
    for (int off = 16; off > 0; off >>= 1) {
        s0 += __shfl_xor_sync(0xffffffffu, s0, off);
        s1 += __shfl_xor_sync(0xffffffffu, s1, off);
        s2 += __shfl_xor_sync(0xffffffffu, s2, off);
    }
    if (lane == 0) { sh0[wid] = s0; sh1[wid] = s1; sh2[wid] = s2; }
    __syncthreads();
    if (wid == 0) {
        s0 = (lane < NWARP) ? sh0[lane] : 0.0f;
        s1 = (lane < NWARP) ? sh1[lane] : 0.0f;
        s2 = (lane < NWARP) ? sh2[lane] : 0.0f;
#pragma unroll
        for (int off = 4; off > 0; off >>= 1) {
            s0 += __shfl_xor_sync(0xffffffffu, s0, off);
            s1 += __shfl_xor_sync(0xffffffffu, s1, off);
            s2 += __shfl_xor_sync(0xffffffffu, s2, off);
        }
        if (lane == 0) {
            atomicAdd(&g_sums[0], s0);
            atomicAdd(&g_sums[1], s1);
            atomicAdd(&g_sums[2], s2);
        }
    }

    // ---- last block writes the final scalar ----
    __threadfence();
    if (tid == 0)
        s_last = (atomicAdd(&g_ctr_red, 1u) == (unsigned)(nblocks - 1));
    __syncthreads();
    if (s_last && tid == 0) {
        __threadfence();
        out[0] = (g_sums[0] + g_sums[1]) / g_sums[2];
    }
}

extern "C" void kernel_launch(void* const* d_in, const int* in_sizes, int n_in,
                              void* d_out, int out_size) {
    const float2* locs   = (const float2*)d_in[0];
    const float*  params = (const float*)d_in[1];
    const float4* truths = (const float4*)d_in[2];
    int P = in_sizes[0] / 2;
    int T = in_sizes[2] / 4;

    int tch     = (T + NTCH - 1) / NTCH;   // 32 for T=512
    int pblocks = (P + PPB - 1) / PPB;     // 32 for P=65536
    int nmain   = pblocks * NTCH;          // 512 blocks

    k_init<<<(P + 255) / 256, 256>>>(P, T);
    k_main<<<nmain, NT>>>(locs, params, truths, P, T, pblocks, tch, nmain);
    int nred = (P + NT * 4 - 1) / (NT * 4);
    k_reduce<<<nred, NT>>>(params, (float*)d_out, P, nred);
}

// round 5
// speedup vs baseline: 2.9568x; 1.1269x over previous
#include <cuda_runtime.h>
#include <cstdint>

#define NT     256
#define PPT    7
#define NTCH   8
#define MAXT   512
#define MAXP   65536
#define NWARP  (NT / 32)
#define PPB    (NT * PPT)   // 1792 priors per block
#define TCHMAX 64

// Scratch — zero-initialized at module load; every call restores zeros itself.
__device__ unsigned long long g_best[MAXT];          // per-truth packed (r_bits<<32 | ~p)
__device__ unsigned long long g_scatter[MAXP];       // per-prior packed ((t+1)<<32 | iou_bits)
__device__ float              g_bto_part[NTCH * MAXP]; // per-(tchunk, prior) max r (plain writes)
__device__ float              g_sums[3];
__device__ unsigned           g_ctr_main;
__device__ unsigned           g_ctr_red;

__global__ void __launch_bounds__(NT, 2)
k_main(const float2* __restrict__ locs,
       const float*  __restrict__ params,
       const float4* __restrict__ truths,
       int P, int T, int pblocks, int tch, int nblocks) {
    __shared__ float4 s_tr[TCHMAX];
    __shared__ float  s_ta[TCHMAX];
    __shared__ unsigned long long s_best[TCHMAX * NWARP]; // 512 u64 (reused by last block)
    __shared__ bool   s_last;

    const int pb  = blockIdx.x % pblocks;
    const int tc  = blockIdx.x / pblocks;
    const int t0  = tc * tch;
    const int t1  = min(min(t0 + tch, T), t0 + TCHMAX);
    const int tid = threadIdx.x;
    const int lane = tid & 31;
    const int wid  = tid >> 5;

    for (int t = t0 + tid; t < t1; t += NT) {
        float4 tb = truths[t];
        s_tr[t - t0] = tb;
        s_ta[t - t0] = (tb.z - tb.x) * (tb.w - tb.y);
    }
    __syncthreads();

    const int pbase = pb * PPB + tid;

    float x0[PPT], y0[PPT], x1[PPT], y1[PPT], ab[PPT], br[PPT];
#pragma unroll
    for (int j = 0; j < PPT; j++) {
        int p = pbase + j * NT;
        float cx, cy, w, h;
        if (p < P) {
            float2 c = locs[p];
            cx = c.x; cy = c.y;
            w = params[3 * p];
            h = params[3 * p + 1];
        } else {
            cx = -1e3f; cy = -1e3f; w = 0.0f; h = 0.0f;
        }
        x0[j] = cx - 0.5f * w;  x1[j] = cx + 0.5f * w;
        y0[j] = cy - 0.5f * h;  y1[j] = cy + 0.5f * h;
        ab[j] = w * h;
        br[j] = 0.0f;           // max r over t (r = inter/S, order-equivalent to iou)
    }

    for (int tt = t0; tt < t1; ++tt) {
        const float4 tb = s_tr[tt - t0];
        const float  ta = s_ta[tt - t0];

        float btr = -1.0f;
        int   btp = pbase;

#pragma unroll
        for (int j = 0; j < PPT; j++) {
            float dx    = fminf(x1[j], tb.z) - fmaxf(x0[j], tb.x);
            float dy    = fminf(y1[j], tb.w) - fmaxf(y0[j], tb.y);
            float inter = fmaxf(dx, 0.0f) * fmaxf(dy, 0.0f);
            float S     = ta + ab[j];               // sum of areas, > 0
            float r     = __fdividef(inter, S);     // MUFU-pipe; iou = r/(1-r) monotone
            br[j] = fmaxf(br[j], r);
            if (r > btr) { btr = r; btp = pbase + j * NT; }
        }

        // warp argmax: pack (r_bits, ~p); ~p => ties prefer smallest prior index
        unsigned long long m =
            (((unsigned long long)__float_as_uint(btr)) << 32) |
            (unsigned int)(~btp);
#pragma unroll
        for (int off = 16; off > 0; off >>= 1) {
            unsigned long long o = __shfl_xor_sync(0xffffffffu, m, off);
            if (o > m) m = o;
        }
        if (lane == 0) s_best[(tt - t0) * NWARP + wid] = m;
    }
    __syncthreads();

    // block combine + one global atomic per truth per block
    for (int tt = t0 + tid; tt < t1; tt += NT) {
        unsigned long long m = s_best[(tt - t0) * NWARP];
#pragma unroll
        for (int w = 1; w < NWARP; w++) {
            unsigned long long v = s_best[(tt - t0) * NWARP + w];
            if (v > m) m = v;
        }
        atomicMax(&g_best[tt], m);
    }

    // per-(tchunk, prior) partial max-r (plain writes; no init needed)
    float* part = g_bto_part + (size_t)tc * MAXP;
#pragma unroll
    for (int j = 0; j < PPT; j++) {
        int p = pbase + j * NT;
        if (p < P) part[p] = br[j];
    }

    // ---- last block: scatter exact iou at each truth's argmax prior ----
    __threadfence();
    if (tid == 0)
        s_last = (atomicAdd(&g_ctr_main, 1u) == (unsigned)(nblocks - 1));
    __syncthreads();
    if (s_last) {
        __threadfence();
        // pass 1: stash winners in smem, clear this call's scatter targets
        for (int t = tid; t < T; t += NT) {
            unsigned long long m = g_best[t];
            s_best[t] = m;                         // TCHMAX*NWARP == 512 slots
            unsigned int p = ~((unsigned int)(m & 0xffffffffull));
            g_scatter[p] = 0ull;                   // same-value concurrent writes OK
            g_best[t] = 0ull;                      // restore zeros for next call
        }
        __threadfence();
        __syncthreads();
        // pass 2: exact iou + last-t-wins scatter
        for (int t = tid; t < T; t += NT) {
            unsigned long long m = s_best[t];
            unsigned int p = ~((unsigned int)(m & 0xffffffffull));
            float4 tb = truths[t];
            float2 c  = locs[p];
            float w = params[3 * p];
            float h = params[3 * p + 1];
            float dx = fminf(c.x + 0.5f * w, tb.z) - fmaxf(c.x - 0.5f * w, tb.x);
            float dy = fminf(c.y + 0.5f * h, tb.w) - fmaxf(c.y - 0.5f * h, tb.y);
            float inter = fmaxf(dx, 0.0f) * fmaxf(dy, 0.0f);
            float ta = (tb.z - tb.x) * (tb.w - tb.y);
            float iou = inter / (ta + w * h - inter);   // exact division
            unsigned long long pk =
                (((unsigned long long)(t + 1)) << 32) | __float_as_uint(iou);
            atomicMax(&g_scatter[p], pk);
        }
        if (tid == 0) g_ctr_main = 0u;             // restore for next call
    }
}

__global__ void __launch_bounds__(NT)
k_reduce(const float* __restrict__ params,
         float* __restrict__ out, int P, int nblocks) {
    __shared__ float sh0[NWARP], sh1[NWARP], sh2[NWARP];
    __shared__ bool  s_last;
    const int tid  = threadIdx.x;
    const int lane = tid & 31;
    const int wid  = tid >> 5;
    const int base = (blockIdx.x * blockDim.x + tid) * 4;

    float s0 = 0.0f, s1 = 0.0f, s2 = 0.0f;
#pragma unroll
    for (int j = 0; j < 4; j++) {
        int p = base + j;
        if (p < P) {
            float r = g_bto_part[p];
#pragma unroll
            for (int c = 1; c < NTCH; c++)
                r = fmaxf(r, g_bto_part[c * MAXP + p]);
            float bto = __fdividef(r, 1.0f - r);       // r <= 0.5 always
            unsigned long long sc = g_scatter[p];
            bool isbest = (sc != 0ull);
            if (isbest) {
                bto = __uint_as_float((unsigned int)(sc & 0xffffffffull));
                g_scatter[p] = 0ull;                   // restore zeros for next call
            }
            float xf = isbest ? 5.0f : (bto > 0.5f ? 1.0f : 0.0f);
            float a = params[3 * p + 2];
            float sig = 1.0f / (1.0f + __expf(-a));
            s0 += sig * xf * bto;
            s1 += sig;          // BETA = 1
            s2 += xf;
        }
    }
#pragma unroll
    for (int off = 16; off > 0; off >>= 1) {
        s0 += __shfl_xor_sync(0xffffffffu, s0, off);
        s1 += __shfl_xor_sync(0xffffffffu, s1, off);
        s2 += __shfl_xor_sync(0xffffffffu, s2, off);
    }
    if (lane == 0) { sh0[wid] = s0; sh1[wid] = s1; sh2[wid] = s2; }
    __syncthreads();
    if (wid == 0) {
        s0 = (lane < NWARP) ? sh0[lane] : 0.0f;
        s1 = (lane < NWARP) ? sh1[lane] : 0.0f;
        s2 = (lane < NWARP) ? sh2[lane] : 0.0f;
#pragma unroll
        for (int off = 4; off > 0; off >>= 1) {
            s0 += __shfl_xor_sync(0xffffffffu, s0, off);
            s1 += __shfl_xor_sync(0xffffffffu, s1, off);
            s2 += __shfl_xor_sync(0xffffffffu, s2, off);
        }
        if (lane == 0) {
            atomicAdd(&g_sums[0], s0);
            atomicAdd(&g_sums[1], s1);
            atomicAdd(&g_sums[2], s2);
        }
    }

    __threadfence();
    if (tid == 0)
        s_last = (atomicAdd(&g_ctr_red, 1u) == (unsigned)(nblocks - 1));
    __syncthreads();
    if (s_last && tid == 0) {
        __threadfence();
        out[0] = (g_sums[0] + g_sums[1]) / g_sums[2];
        g_sums[0] = 0.0f; g_sums[1] = 0.0f; g_sums[2] = 0.0f;  // restore zeros
        g_ctr_red = 0u;
    }
}

extern "C" void kernel_launch(void* const* d_in, const int* in_sizes, int n_in,
                              void* d_out, int out_size) {
    const float2* locs   = (const float2*)d_in[0];
    const float*  params = (const float*)d_in[1];
    const float4* truths = (const float4*)d_in[2];
    int P = in_sizes[0] / 2;
    int T = in_sizes[2] / 4;

    int tch     = (T + NTCH - 1) / NTCH;   // 64 for T=512
    int pblocks = (P + PPB - 1) / PPB;     // 37 for P=65536
    int nmain   = pblocks * NTCH;          // 296 = 148 SMs x occ 2 (single wave)

    k_main<<<nmain, NT>>>(locs, params, truths, P, T, pblocks, tch, nmain);
    int nred = (P + NT * 4 - 1) / (NT * 4);
    k_reduce<<<nred, NT>>>(params, (float*)d_out, P, nred);
}

// round 8
// speedup vs baseline: 2.9749x; 1.0061x over previous
#include <cuda_runtime.h>
#include <cstdint>

#define NT     256
#define PPT    7
#define NTCH   8
#define MAXT   512
#define MAXP   65536
#define NWARP  (NT / 32)
#define PPB    (NT * PPT)   // 1792 priors per block
#define TCHMAX 64
#define FULLM  0xffffffffu

// Scratch — zero-initialized at module load; every call restores zeros itself.
__device__ unsigned long long g_best[MAXT];     // per-truth packed (r_bits<<32 | ~p)
__device__ unsigned long long g_scatter[MAXP];  // per-prior packed ((t+1)<<32 | iou_bits)
__device__ unsigned           g_bto[MAXP];      // per-prior max packed-r (float bits, >=0)
__device__ float              g_sums[3];
__device__ unsigned           g_ctr_main;
__device__ unsigned           g_ctr_red;

__global__ void __launch_bounds__(NT, 2)
k_main(const float2* __restrict__ locs,
       const float*  __restrict__ params,
       const float4* __restrict__ truths,
       int P, int T, int pblocks, int tch, int nblocks) {
    __shared__ float4 s_tr[TCHMAX];
    __shared__ float  s_ta[TCHMAX];
    __shared__ unsigned long long s_best[TCHMAX * NWARP]; // 512 u64 (reused by last block)
    __shared__ bool   s_last;

    const int pb  = blockIdx.x % pblocks;
    const int tc  = blockIdx.x / pblocks;
    const int t0  = tc * tch;
    const int t1  = min(min(t0 + tch, T), t0 + TCHMAX);
    const int tid = threadIdx.x;
    const int lane = tid & 31;
    const int wid  = tid >> 5;

    for (int t = t0 + tid; t < t1; t += NT) {
        float4 tb = truths[t];
        s_tr[t - t0] = tb;
        s_ta[t - t0] = (tb.z - tb.x) * (tb.w - tb.y);
    }
    __syncthreads();

    const int pbase = pb * PPB + tid;

    float x0[PPT], y0[PPT], x1[PPT], y1[PPT], ab[PPT], br[PPT];
#pragma unroll
    for (int j = 0; j < PPT; j++) {
        int p = pbase + j * NT;
        float cx, cy, w, h;
        if (p < P) {
            float2 c = locs[p];
            cx = c.x; cy = c.y;
            w = params[3 * p];
            h = params[3 * p + 1];
        } else {
            cx = -1e3f; cy = -1e3f; w = 0.0f; h = 0.0f;
        }
        x0[j] = cx - 0.5f * w;  x1[j] = cx + 0.5f * w;
        y0[j] = cy - 0.5f * h;  y1[j] = cy + 0.5f * h;
        ab[j] = w * h;
        br[j] = 0.0f;           // max packed-r over t
    }

    for (int tt = t0; tt < t1; ++tt) {
        const float4 tb = s_tr[tt - t0];
        const float  ta = s_ta[tt - t0];

        float btr = 0.0f;       // max packed-r over this thread's priors for truth tt

#pragma unroll
        for (int j = 0; j < PPT; j++) {
            float dx    = fminf(x1[j], tb.z) - fmaxf(x0[j], tb.x);
            float dy    = fminf(y1[j], tb.w) - fmaxf(y0[j], tb.y);
            float inter = fmaxf(dx, 0.0f) * fmaxf(dy, 0.0f);
            float S     = ta + ab[j];               // sum of areas, > 0
            float r     = __fdividef(inter, S);     // MUFU; iou = r/(1-r) monotone
            // pack j into low 3 mantissa bits: argmax becomes a pure max
            float rp = __uint_as_float((__float_as_uint(r) & ~7u) | (unsigned)j);
            br[j] = fmaxf(br[j], rp);
            btr   = fmaxf(btr, rp);
        }

        // warp max (scalar float), then recover the winning lane via ballot
        float mybtr = btr;
#pragma unroll
        for (int off = 16; off > 0; off >>= 1)
            btr = fmaxf(btr, __shfl_xor_sync(FULLM, btr, off));
        unsigned ball = __ballot_sync(FULLM, mybtr == btr);
        if (lane == 0) {
            int lane_w = __ffs(ball) - 1;
            int j_w    = (int)(__float_as_uint(btr) & 7u);
            int p_w    = pb * PPB + wid * 32 + lane_w + j_w * NT;
            s_best[(tt - t0) * NWARP + wid] =
                (((unsigned long long)__float_as_uint(btr)) << 32) |
                (unsigned int)(~p_w);
        }
    }
    __syncthreads();

    // block combine + one global atomic per truth per block
    for (int tt = t0 + tid; tt < t1; tt += NT) {
        unsigned long long m = s_best[(tt - t0) * NWARP];
#pragma unroll
        for (int w = 1; w < NWARP; w++) {
            unsigned long long v = s_best[(tt - t0) * NWARP + w];
            if (v > m) m = v;
        }
        atomicMax(&g_best[tt], m);
    }

    // per-prior best overlap via float-bits atomicMax (values >= 0)
#pragma unroll
    for (int j = 0; j < PPT; j++) {
        int p = pbase + j * NT;
        if (p < P) atomicMax(&g_bto[p], __float_as_uint(br[j]));
    }

    // ---- last block: scatter exact iou at each truth's argmax prior ----
    __threadfence();
    if (tid == 0)
        s_last = (atomicAdd(&g_ctr_main, 1u) == (unsigned)(nblocks - 1));
    __syncthreads();
    if (s_last) {
        __threadfence();
        // pass 1: stash winners in smem, clear targets, restore g_best zeros
        for (int t = tid; t < T; t += NT) {
            unsigned long long m = g_best[t];
            s_best[t] = m;                               // TCHMAX*NWARP == 512 slots
            unsigned int p = (~((unsigned int)(m & 0xffffffffull))) & (MAXP - 1u);
            g_scatter[p] = 0ull;
            g_best[t] = 0ull;
        }
        __threadfence();
        __syncthreads();
        // pass 2: exact iou + last-t-wins scatter
        for (int t = tid; t < T; t += NT) {
            unsigned long long m = s_best[t];
            unsigned int p = (~((unsigned int)(m & 0xffffffffull))) & (MAXP - 1u);
            float4 tb = truths[t];
            float2 c  = locs[p];
            float w = params[3 * p];
            float h = params[3 * p + 1];
            float dx = fminf(c.x + 0.5f * w, tb.z) - fmaxf(c.x - 0.5f * w, tb.x);
            float dy = fminf(c.y + 0.5f * h, tb.w) - fmaxf(c.y - 0.5f * h, tb.y);
            float inter = fmaxf(dx, 0.0f) * fmaxf(dy, 0.0f);
            float ta = (tb.z - tb.x) * (tb.w - tb.y);
            float iou = inter / (ta + w * h - inter);   // exact division
            unsigned long long pk =
                (((unsigned long long)(t + 1)) << 32) | __float_as_uint(iou);
            atomicMax(&g_scatter[p], pk);
        }
        if (tid == 0) g_ctr_main = 0u;
    }
}

__global__ void __launch_bounds__(NT)
k_reduce(const float* __restrict__ params,
         float* __restrict__ out, int P, int nblocks) {
    __shared__ float sh0[NWARP], sh1[NWARP], sh2[NWARP];
    __shared__ bool  s_last;
    const int tid  = threadIdx.x;
    const int lane = tid & 31;
    const int wid  = tid >> 5;
    const int base = blockIdx.x * (NT * 2) + tid;

    float s0 = 0.0f, s1 = 0.0f, s2 = 0.0f;
#pragma unroll
    for (int j = 0; j < 2; j++) {
        int p = base + j * NT;
        if (p < P) {
            float r = __uint_as_float(g_bto[p]);
            g_bto[p] = 0u;                             // restore zeros for next call
            float bto = __fdividef(r, 1.0f - r);       // r <= 0.5 always
            unsigned long long sc = g_scatter[p];
            bool isbest = (sc != 0ull);
            if (isbest) {
                bto = __uint_as_float((unsigned int)(sc & 0xffffffffull));
                g_scatter[p] = 0ull;                   // restore zeros for next call
            }
            float xf = isbest ? 5.0f : (bto > 0.5f ? 1.0f : 0.0f);
            float a = params[3 * p + 2];
            float sig = 1.0f / (1.0f + __expf(-a));
            s0 += sig * xf * bto;
            s1 += sig;          // BETA = 1
            s2 += xf;
        }
    }
#pragma unroll
    for (int off = 16; off > 0; off >>= 1) {
        s0 += __shfl_xor_sync(FULLM, s0, off);
        s1 += __shfl_xor_sync(FULLM, s1, off);
        s2 += __shfl_xor_sync(FULLM, s2, off);
    }
    if (lane == 0) { sh0[wid] = s0; sh1[wid] = s1; sh2[wid] = s2; }
    __syncthreads();
    if (wid == 0) {
        s0 = (lane < NWARP) ? sh0[lane] : 0.0f;
        s1 = (lane < NWARP) ? sh1[lane] : 0.0f;
        s2 = (lane < NWARP) ? sh2[lane] : 0.0f;
#pragma unroll
        for (int off = 4; off > 0; off >>= 1) {
            s0 += __shfl_xor_sync(FULLM, s0, off);
            s1 += __shfl_xor_sync(FULLM, s1, off);
            s2 += __shfl_xor_sync(FULLM, s2, off);
        }
        if (lane == 0) {
            atomicAdd(&g_sums[0], s0);
            atomicAdd(&g_sums[1], s1);
            atomicAdd(&g_sums[2], s2);
        }
    }

    __threadfence();
    if (tid == 0)
        s_last = (atomicAdd(&g_ctr_red, 1u) == (unsigned)(nblocks - 1));
    __syncthreads();
    if (s_last && tid == 0) {
        __threadfence();
        out[0] = (g_sums[0] + g_sums[1]) / g_sums[2];
        g_sums[0] = 0.0f; g_sums[1] = 0.0f; g_sums[2] = 0.0f;
        g_ctr_red = 0u;
    }
}

extern "C" void kernel_launch(void* const* d_in, const int* in_sizes, int n_in,
                              void* d_out, int out_size) {
    const float2* locs   = (const float2*)d_in[0];
    const float*  params = (const float*)d_in[1];
    const float4* truths = (const float4*)d_in[2];
    int P = in_sizes[0] / 2;
    int T = in_sizes[2] / 4;

    int tch     = (T + NTCH - 1) / NTCH;   // 64 for T=512
    int pblocks = (P + PPB - 1) / PPB;     // 37 for P=65536
    int nmain   = pblocks * NTCH;          // 296 = 148 SMs x occ 2 (single wave)

    k_main<<<nmain, NT>>>(locs, params, truths, P, T, pblocks, tch, nmain);
    int nred = (P + NT * 2 - 1) / (NT * 2);  // 128 blocks
    k_reduce<<<nred, NT>>>(params, (float*)d_out, P, nred);
}